// round 4
// baseline (speedup 1.0000x reference)
#include <cuda_runtime.h>
#include <cuda_bf16.h>

// Problem constants
#define BATCH   2
#define SEQ     2048
#define DMODEL  1024
#define NHEAD   16
#define DK      64
#define MROWS   (BATCH * SEQ)       // 4096

// ---------------------------------------------------------------------------
// Scratch (no allocations allowed -> device globals)
// ---------------------------------------------------------------------------
__device__ float g_Q[MROWS * DMODEL];
__device__ float g_K[MROWS * DMODEL];
__device__ float g_V[MROWS * DMODEL];
__device__ float g_X[MROWS * DMODEL];   // attention output (pre out-proj)

// ---------------------------------------------------------------------------
// Packed fp32x2 helpers (Blackwell double-rate fp32 path)
// ---------------------------------------------------------------------------
__device__ __forceinline__ unsigned long long pack2(float lo, float hi) {
    unsigned long long r;
    asm("mov.b64 %0, {%1, %2};" : "=l"(r) : "f"(lo), "f"(hi));
    return r;
}
__device__ __forceinline__ float2 unpack2(unsigned long long x) {
    float2 r;
    asm("mov.b64 {%0, %1}, %2;" : "=f"(r.x), "=f"(r.y) : "l"(x));
    return r;
}
__device__ __forceinline__ unsigned long long ffma2(unsigned long long a,
                                                    unsigned long long b,
                                                    unsigned long long c) {
    unsigned long long d;
    asm("fma.rn.f32x2 %0, %1, %2, %3;" : "=l"(d) : "l"(a), "l"(b), "l"(c));
    return d;
}
__device__ __forceinline__ unsigned long long fmul2(unsigned long long a,
                                                    unsigned long long b) {
    unsigned long long d;
    asm("mul.rn.f32x2 %0, %1, %2;" : "=l"(d) : "l"(a), "l"(b));
    return d;
}

// ---------------------------------------------------------------------------
// NT GEMM body: C[m,n] = sum_k A[m,k] * W[n,k];  M-tile 128, N-tile 128, K-tile 16
// K = N = 1024 fixed. 256 threads; each thread: 8 rows x 4 packed col-pairs.
// Thread (ty,tx): rows m0+ty*8..+7, cols n0 + 2*tx + 32*p + {0,1}, p=0..3.
// A is stored DUPLICATED in smem so f32x2 'a' operand loads need no packing.
// ---------------------------------------------------------------------------
__device__ __forceinline__ void gemm_nt_body(const float* __restrict__ A,
                                             const float* __restrict__ W,
                                             float* __restrict__ C) {
    __shared__ __align__(16) float As2[16][256];   // [k][2*m] duplicated
    __shared__ __align__(16) float Bs[16][128];    // [k][n]

    const int tid = threadIdx.x;
    const int m0 = blockIdx.y * 128;
    const int n0 = blockIdx.x * 128;
    const int ty = tid >> 4;      // 0..15
    const int tx = tid & 15;      // 0..15

    // load-phase mapping: two float4 per thread per tile for A and for B
    const int r0 = tid >> 2;      // 0..63
    const int r1 = r0 + 64;
    const int c4 = tid & 3;       // float4 column within 16-wide k slab

    const float4* A4 = (const float4*)A;
    const float4* W4 = (const float4*)W;

    unsigned long long acc[8][4];
#pragma unroll
    for (int i = 0; i < 8; i++)
#pragma unroll
        for (int p = 0; p < 4; p++) acc[i][p] = 0ull;

    // prefetch kt = 0
    float4 pa0 = A4[(size_t)(m0 + r0) * 256 + c4];
    float4 pa1 = A4[(size_t)(m0 + r1) * 256 + c4];
    float4 pb0 = W4[(size_t)(n0 + r0) * 256 + c4];
    float4 pb1 = W4[(size_t)(n0 + r1) * 256 + c4];

    for (int kt = 0; kt < 64; kt++) {
        // ---- stage tile into smem (A duplicated) ----
        {
            const int kc = c4 * 4;
            *(float2*)&As2[kc + 0][2 * r0] = make_float2(pa0.x, pa0.x);
            *(float2*)&As2[kc + 1][2 * r0] = make_float2(pa0.y, pa0.y);
            *(float2*)&As2[kc + 2][2 * r0] = make_float2(pa0.z, pa0.z);
            *(float2*)&As2[kc + 3][2 * r0] = make_float2(pa0.w, pa0.w);
            *(float2*)&As2[kc + 0][2 * r1] = make_float2(pa1.x, pa1.x);
            *(float2*)&As2[kc + 1][2 * r1] = make_float2(pa1.y, pa1.y);
            *(float2*)&As2[kc + 2][2 * r1] = make_float2(pa1.z, pa1.z);
            *(float2*)&As2[kc + 3][2 * r1] = make_float2(pa1.w, pa1.w);
            Bs[kc + 0][r0] = pb0.x;
            Bs[kc + 1][r0] = pb0.y;
            Bs[kc + 2][r0] = pb0.z;
            Bs[kc + 3][r0] = pb0.w;
            Bs[kc + 0][r1] = pb1.x;
            Bs[kc + 1][r1] = pb1.y;
            Bs[kc + 2][r1] = pb1.z;
            Bs[kc + 3][r1] = pb1.w;
        }
        __syncthreads();

        // ---- prefetch next tile while computing this one ----
        if (kt < 63) {
            const int ko = (kt + 1) * 4;
            pa0 = A4[(size_t)(m0 + r0) * 256 + ko + c4];
            pa1 = A4[(size_t)(m0 + r1) * 256 + ko + c4];
            pb0 = W4[(size_t)(n0 + r0) * 256 + ko + c4];
            pb1 = W4[(size_t)(n0 + r1) * 256 + ko + c4];
        }

        // ---- compute 16 k-steps ----
#pragma unroll
        for (int kk = 0; kk < 16; kk++) {
            unsigned long long a2[8];
            const ulonglong2* Ar = (const ulonglong2*)&As2[kk][ty * 16];
#pragma unroll
            for (int i = 0; i < 4; i++) {
                ulonglong2 t = Ar[i];
                a2[2 * i]     = t.x;
                a2[2 * i + 1] = t.y;
            }
            unsigned long long b2[4];
#pragma unroll
            for (int p = 0; p < 4; p++)
                b2[p] = *(const unsigned long long*)&Bs[kk][2 * tx + 32 * p];
#pragma unroll
            for (int i = 0; i < 8; i++)
#pragma unroll
                for (int p = 0; p < 4; p++)
                    acc[i][p] = ffma2(a2[i], b2[p], acc[i][p]);
        }
        __syncthreads();
    }

    // ---- epilogue: packed pair == two adjacent fp32 in memory ----
    float* Cr = C + (size_t)(m0 + ty * 8) * 1024 + n0 + 2 * tx;
#pragma unroll
    for (int i = 0; i < 8; i++)
#pragma unroll
        for (int p = 0; p < 4; p++)
            *(unsigned long long*)(Cr + (size_t)i * 1024 + 32 * p) = acc[i][p];
}

// Fused Q/K/V projection: blockIdx.z selects which projection (better wave balance)
__global__ void __launch_bounds__(256)
mha_gemm_qkv(const float* __restrict__ q, const float* __restrict__ k,
             const float* __restrict__ v, const float* __restrict__ wq,
             const float* __restrict__ wk, const float* __restrict__ wv) {
    const int z = blockIdx.z;
    const float* A = (z == 0) ? q : (z == 1) ? k : v;
    const float* W = (z == 0) ? wq : (z == 1) ? wk : wv;
    float* C = (z == 0) ? g_Q : (z == 1) ? g_K : g_V;
    gemm_nt_body(A, W, C);
}

__global__ void __launch_bounds__(256)
mha_gemm_out(const float* __restrict__ wo, float* __restrict__ out) {
    gemm_nt_body(g_X, wo, out);
}

// ---------------------------------------------------------------------------
// Flash attention: one CTA = 128 query rows of one (batch, head).
// 128 threads, thread t owns query row q0+t. q and O accumulators live in
// packed-u64 registers; K/V tiles (64x64 fp32) in smem read as broadcast
// ulonglong2; scores staged in smem (stride 65 -> conflict-free).
// ---------------------------------------------------------------------------
#define ATT_BM 128
#define ATT_BN 64
#define ATT_SS_STRIDE 65
#define ATT_SMEM_BYTES ((2 * ATT_BN * DK + ATT_BM * ATT_SS_STRIDE) * 4)

__global__ void __launch_bounds__(128)
mha_flash_attn(const int* __restrict__ mask) {
    extern __shared__ float smf[];
    float* Ks = smf;                       // [64][64]
    float* Vs = smf + ATT_BN * DK;         // [64][64]
    float* Ss = smf + 2 * ATT_BN * DK;     // [128][65]

    const int t  = threadIdx.x;
    const int q0 = blockIdx.x * ATT_BM;
    const int bh = blockIdx.y;
    const int b  = bh >> 4;
    const int h  = bh & 15;
    const int row = b * SEQ + q0 + t;      // row into [B*S, D]

    // load q row (64 floats) as 32 packed pairs
    unsigned long long q2[32];
    {
        const ulonglong2* Qr =
            (const ulonglong2*)(g_Q + (size_t)row * DMODEL + h * DK);
#pragma unroll
        for (int i = 0; i < 16; i++) {
            ulonglong2 tq = Qr[i];
            q2[2 * i]     = tq.x;
            q2[2 * i + 1] = tq.y;
        }
    }
    unsigned long long o2[32];
#pragma unroll
    for (int i = 0; i < 32; i++) o2[i] = 0ull;

    float m_i = -1e30f;
    float l_i = 0.0f;

    const int* mrow = mask + ((size_t)b * SEQ + (q0 + t)) * SEQ;
    float* ssrow = Ss + t * ATT_SS_STRIDE;

    const float4* K4base = (const float4*)g_K;
    const float4* V4base = (const float4*)g_V;

    for (int j0 = 0; j0 < SEQ; j0 += ATT_BN) {
        // ---- cooperative K/V tile load: 64 rows x 16 float4 each ----
        {
            const size_t base = (size_t)(b * SEQ + j0) * 256 + h * 16;
#pragma unroll
            for (int it = 0; it < 8; it++) {
                const int i = t + it * 128;
                const int r = i >> 4, c = i & 15;
                ((float4*)Ks)[i] = K4base[base + (size_t)r * 256 + c];
                ((float4*)Vs)[i] = V4base[base + (size_t)r * 256 + c];
            }
        }
        __syncthreads();

        // ---- scores: s_j = (q . K_j) / 8, masked ----
        float tmax = -1e30f;
#pragma unroll 2
        for (int j4 = 0; j4 < ATT_BN / 4; j4++) {
            const int4 mv = *(const int4*)(mrow + j0 + j4 * 4);
            const int mvals[4] = {mv.x, mv.y, mv.z, mv.w};
#pragma unroll
            for (int jj = 0; jj < 4; jj++) {
                const int j = j4 * 4 + jj;
                const ulonglong2* k2 = (const ulonglong2*)(Ks + j * DK);
                unsigned long long acc0 = 0ull, acc1 = 0ull;
#pragma unroll
                for (int c = 0; c < 16; c++) {
                    ulonglong2 kv = k2[c];
                    acc0 = ffma2(q2[2 * c],     kv.x, acc0);
                    acc1 = ffma2(q2[2 * c + 1], kv.y, acc1);
                }
                float2 a0 = unpack2(acc0);
                float2 a1 = unpack2(acc1);
                float s = (a0.x + a0.y + a1.x + a1.y) * 0.125f;
                if (mvals[jj] == 0) s = -1e9f;
                ssrow[j] = s;
                tmax = fmaxf(tmax, s);
            }
        }

        // ---- online softmax rescale ----
        const float m_new = fmaxf(m_i, tmax);
        const float alpha = __expf(m_i - m_new);
        l_i *= alpha;
        {
            const unsigned long long a2 = pack2(alpha, alpha);
#pragma unroll
            for (int c = 0; c < 32; c++) o2[c] = fmul2(o2[c], a2);
        }

        // ---- accumulate P @ V ----
        for (int j = 0; j < ATT_BN; j++) {
            const float p = __expf(ssrow[j] - m_new);
            l_i += p;
            const unsigned long long p2 = pack2(p, p);
            const ulonglong2* v2 = (const ulonglong2*)(Vs + j * DK);
#pragma unroll
            for (int c = 0; c < 16; c++) {
                ulonglong2 vv = v2[c];
                o2[2 * c]     = ffma2(p2, vv.x, o2[2 * c]);
                o2[2 * c + 1] = ffma2(p2, vv.y, o2[2 * c + 1]);
            }
        }
        m_i = m_new;
        __syncthreads();
    }

    // ---- epilogue: O = acc / l ----
    const float inv = 1.0f / l_i;
    const unsigned long long inv2 = pack2(inv, inv);
    unsigned long long* Or =
        (unsigned long long*)(g_X + (size_t)row * DMODEL + h * DK);
#pragma unroll
    for (int c = 0; c < 32; c++) Or[c] = fmul2(o2[c], inv2);
}

// ---------------------------------------------------------------------------
// Launch
// Inputs (metadata order): q, k, v, w_q, w_k, w_v, w_o, mask
// ---------------------------------------------------------------------------
extern "C" void kernel_launch(void* const* d_in, const int* in_sizes, int n_in,
                              void* d_out, int out_size) {
    const float* q  = (const float*)d_in[0];
    const float* k  = (const float*)d_in[1];
    const float* v  = (const float*)d_in[2];
    const float* wq = (const float*)d_in[3];
    const float* wk = (const float*)d_in[4];
    const float* wv = (const float*)d_in[5];
    const float* wo = (const float*)d_in[6];
    const int* mask = (const int*)d_in[7];
    float* out = (float*)d_out;

    cudaFuncSetAttribute(mha_flash_attn,
                         cudaFuncAttributeMaxDynamicSharedMemorySize,
                         ATT_SMEM_BYTES);

    // Q/K/V projections: grid (N/128, M/128, 3)
    dim3 gqkv(DMODEL / 128, MROWS / 128, 3);
    mha_gemm_qkv<<<gqkv, 256>>>(q, k, v, wq, wk, wv);

    // attention: grid (S/128, B*H)
    dim3 gatt(SEQ / ATT_BM, BATCH * NHEAD);
    mha_flash_attn<<<gatt, 128, ATT_SMEM_BYTES>>>(mask);

    // output projection
    dim3 gout(DMODEL / 128, MROWS / 128, 1);
    mha_gemm_out<<<gout, 256>>>(wo, out);
}